// round 1
// baseline (speedup 1.0000x reference)
#include <cuda_runtime.h>
#include <math.h>

#define NN   4096
#define FF   256
#define ELLW 256
#define NE   (NN * NN)

// ---------------- scratch (device globals: no allocation allowed) ----------------
__device__ float g_A[NE];              // dense adjacency (rebuilt every call)
__device__ float g_colsum[NN];
__device__ float g_rowsum[NN];
__device__ float g_dinv[NN];
__device__ int   g_cnt[NN];            // ELL per-row nnz
__device__ int   g_col[NN * ELLW];
__device__ float g_lre[NN * ELLW];
__device__ float g_lim[NN * ELLW];
__device__ float g_Z1r[NN * FF], g_Z1i[NN * FF];
__device__ float g_Z2r[NN * FF], g_Z2i[NN * FF];
__device__ float g_H1r[NN * FF], g_H1i[NN * FF];
__device__ float g_H2r[NN * FF], g_H2i[NN * FF];

// ---------------- kernels ----------------

// Zero A (as float4) + per-row counters + colsum accumulators.
__global__ void zero_kernel() {
    int idx = blockIdx.x * blockDim.x + threadIdx.x;
    float4 z = make_float4(0.f, 0.f, 0.f, 0.f);
    if (idx < NE / 4) reinterpret_cast<float4*>(g_A)[idx] = z;
    if (idx < NN) { g_cnt[idx] = 0; g_colsum[idx] = 0.f; }
}

// Scatter-add edges into dense A (duplicates sum, like coo_matrix).
__global__ void scatter_kernel(const int* __restrict__ edges,
                               const float* __restrict__ w, int E) {
    int e = blockIdx.x * blockDim.x + threadIdx.x;
    if (e < E) {
        int r = edges[e];
        int c = edges[E + e];
        atomicAdd(&g_A[r * NN + c], w[e]);
    }
}

// Column sums of A (coalesced), partial per i-chunk via atomics.
__global__ void colsum_kernel() {
    int j  = blockIdx.x * blockDim.x + threadIdx.x; // column
    int i0 = blockIdx.y * 128;
    float s = 0.f;
    #pragma unroll 4
    for (int i = i0; i < i0 + 128; i++) s += g_A[i * NN + j];
    atomicAdd(&g_colsum[j], s);
}

// Row sums of A: one block per row, shared reduction.
__global__ void rowsum_kernel() {
    int row = blockIdx.x;
    int t = threadIdx.x;
    float s = 0.f;
    for (int j = t; j < NN; j += 256) s += g_A[row * NN + j];
    __shared__ float red[256];
    red[t] = s;
    __syncthreads();
    for (int o = 128; o > 0; o >>= 1) {
        if (t < o) red[t] += red[t + o];
        __syncthreads();
    }
    if (t == 0) g_rowsum[row] = red[0];
}

// dinv = (d==0 ? 1 : d)^-0.5 with d = 0.5*(rowsum+colsum)
__global__ void dinv_kernel() {
    int i = blockIdx.x * blockDim.x + threadIdx.x;
    if (i < NN) {
        float d = 0.5f * (g_rowsum[i] + g_colsum[i]);
        if (d == 0.f) d = 1.f;
        g_dinv[i] = rsqrtf(d);
    }
}

// Build ELL-format sparse Lc = -A_n * exp(-i*Theta).
// 32x32 tiles with smem transpose so both A and A^T reads are coalesced.
__global__ void build_ell_kernel(const float* __restrict__ qp) {
    __shared__ float tA[32][33];
    __shared__ float tAT[32][33];
    int tx = threadIdx.x;        // 0..31
    int ty = threadIdx.y;        // 0..7
    int ti = blockIdx.y * 32;    // row tile base
    int tj = blockIdx.x * 32;    // col tile base
    #pragma unroll
    for (int r = 0; r < 4; r++) {
        int ii = ty + r * 8;
        tA [ii][tx] = g_A[(ti + ii) * NN + tj + tx];
        tAT[ii][tx] = g_A[(tj + ii) * NN + ti + tx];
    }
    __syncthreads();
    float q = __ldg(qp);
    #pragma unroll
    for (int r = 0; r < 4; r++) {
        int il = ty + r * 8;
        int i = ti + il;
        int j = tj + tx;
        float a  = tA[il][tx];
        float at = tAT[tx][il];
        float asym = 0.5f * (a + at);
        if (asym != 0.f) {
            float an = g_dinv[i] * asym * g_dinv[j];
            float th = 6.283185307179586f * q * (a - at);
            float sn, cs;
            sincosf(th, &sn, &cs);
            int slot = atomicAdd(&g_cnt[i], 1);
            if (slot < ELLW) {
                g_col[i * ELLW + slot] = j;
                g_lre[i * ELLW + slot] = -an * cs;  // re(conj L)
                g_lim[i * ELLW + slot] =  an * sn;  // im(conj L)
            }
        }
    }
}

// Complex SpMM: Y = Lc @ X  (or Y = 2*(Lc@X) - S when Sr != null).
// One block per row; 256 threads = 256 feature columns.
__global__ void spmm_kernel(const float* __restrict__ Xr, const float* __restrict__ Xi,
                            const float* __restrict__ Sr, const float* __restrict__ Si,
                            float* __restrict__ Yr, float* __restrict__ Yi) {
    int row = blockIdx.x;
    int t = threadIdx.x;
    int cnt = g_cnt[row];
    if (cnt > ELLW) cnt = ELLW;
    __shared__ int   sc[ELLW];
    __shared__ float slr[ELLW];
    __shared__ float sli[ELLW];
    for (int k = t; k < cnt; k += 256) {
        sc [k] = g_col[row * ELLW + k];
        slr[k] = g_lre[row * ELLW + k];
        sli[k] = g_lim[row * ELLW + k];
    }
    __syncthreads();
    float ar = 0.f, ai = 0.f;
    #pragma unroll 4
    for (int k = 0; k < cnt; k++) {
        int   c  = sc[k];
        float lr = slr[k];
        float li = sli[k];
        float xr = __ldg(&Xr[c * FF + t]);
        float xi = __ldg(&Xi[c * FF + t]);
        ar = fmaf(lr, xr, ar);
        ar = fmaf(-li, xi, ar);
        ai = fmaf(lr, xi, ai);
        ai = fmaf(li, xr, ai);
    }
    int o = row * FF + t;
    if (Sr) {
        Yr[o] = 2.f * ar - Sr[o];
        Yi[o] = 2.f * ai - Si[o];
    } else {
        Yr[o] = ar;
        Yi[o] = ai;
    }
}

// C[4096,256] = sign*(A0@W[0] + A1@W[1] + A2@W[2]) + bias  (K = 3*256 = 768)
// Tile 128x64, 256 threads, each thread 8x4 outputs, K-step 16.
__global__ void gemm3_kernel(const float* __restrict__ A0, const float* __restrict__ A1,
                             const float* __restrict__ A2, const float* __restrict__ Wt,
                             const float* __restrict__ bias, float sign,
                             float* __restrict__ C) {
    __shared__ float As[16][132];
    __shared__ float Ws[16][64];
    int tid = threadIdx.x;
    int tx = tid & 15;   // output col group (4 cols)
    int ty = tid >> 4;   // output row group (8 rows)
    int m0 = blockIdx.y * 128;
    int n0 = blockIdx.x * 64;
    float acc[8][4];
    #pragma unroll
    for (int i = 0; i < 8; i++)
        #pragma unroll
        for (int j = 0; j < 4; j++) acc[i][j] = 0.f;

    for (int k0 = 0; k0 < 768; k0 += 16) {
        const float* Ap = (k0 < 256) ? A0 : (k0 < 512 ? A1 : A2);
        int kc = k0 & 255;
        int km = k0 >> 8;
        // load A tile 128x16 -> As[k][m]
        {
            int k = tid & 15;
            int mb = tid >> 4;
            #pragma unroll
            for (int r = 0; r < 8; r++) {
                int m = mb + r * 16;
                As[k][m] = Ap[(m0 + m) * 256 + kc + k];
            }
        }
        // load W tile 16x64 -> Ws[k][n]
        #pragma unroll
        for (int r = 0; r < 4; r++) {
            int idx = tid + r * 256;
            int k = idx >> 6;
            int n = idx & 63;
            Ws[k][n] = Wt[km * 65536 + (kc + k) * 256 + n0 + n];
        }
        __syncthreads();
        #pragma unroll
        for (int k = 0; k < 16; k++) {
            float4 a0 = *reinterpret_cast<const float4*>(&As[k][ty * 8]);
            float4 a1 = *reinterpret_cast<const float4*>(&As[k][ty * 8 + 4]);
            float4 w  = *reinterpret_cast<const float4*>(&Ws[k][tx * 4]);
            float av[8] = {a0.x, a0.y, a0.z, a0.w, a1.x, a1.y, a1.z, a1.w};
            float wv[4] = {w.x, w.y, w.z, w.w};
            #pragma unroll
            for (int i = 0; i < 8; i++)
                #pragma unroll
                for (int j = 0; j < 4; j++)
                    acc[i][j] = fmaf(av[i], wv[j], acc[i][j]);
        }
        __syncthreads();
    }
    float bv[4];
    #pragma unroll
    for (int j = 0; j < 4; j++) bv[j] = bias[n0 + tx * 4 + j];
    #pragma unroll
    for (int i = 0; i < 8; i++) {
        int m = m0 + ty * 8 + i;
        float4 o;
        o.x = sign * acc[i][0] + bv[0];
        o.y = sign * acc[i][1] + bv[1];
        o.z = sign * acc[i][2] + bv[2];
        o.w = sign * acc[i][3] + bv[3];
        *reinterpret_cast<float4*>(&C[m * 256 + n0 + tx * 4]) = o;
    }
}

// logits = [Hr|Hi] @ Wc^T + bc, then log_softmax. One block per node row.
__global__ void classifier_kernel(const float* __restrict__ Hr, const float* __restrict__ Hi,
                                  const float* __restrict__ Wc, const float* __restrict__ bc,
                                  float* __restrict__ out) {
    int row = blockIdx.x;
    int t = threadIdx.x;   // 128
    __shared__ float x[512];
    __shared__ float lg[40];
    for (int i = t; i < 256; i += 128) {
        x[i]       = Hr[row * 256 + i];
        x[i + 256] = Hi[row * 256 + i];
    }
    __syncthreads();
    int warp = t >> 5, lane = t & 31;
    for (int c = warp; c < 40; c += 4) {
        float s = 0.f;
        #pragma unroll
        for (int k = lane; k < 512; k += 32) s = fmaf(x[k], Wc[c * 512 + k], s);
        #pragma unroll
        for (int o = 16; o > 0; o >>= 1) s += __shfl_xor_sync(0xffffffffu, s, o);
        if (lane == 0) lg[c] = s + bc[c];
    }
    __syncthreads();
    if (warp == 0) {
        float a  = (lane < 40)      ? lg[lane]      : -3.4e38f;
        float b2 = (lane + 32 < 40) ? lg[lane + 32] : -3.4e38f;
        float m = fmaxf(a, b2);
        #pragma unroll
        for (int o = 16; o > 0; o >>= 1) m = fmaxf(m, __shfl_xor_sync(0xffffffffu, m, o));
        float s = ((lane < 40) ? expf(a - m) : 0.f) + ((lane + 32 < 40) ? expf(b2 - m) : 0.f);
        #pragma unroll
        for (int o = 16; o > 0; o >>= 1) s += __shfl_xor_sync(0xffffffffu, s, o);
        float lse = m + logf(s);
        if (lane < 40)      out[row * 40 + lane]      = a - lse;
        if (lane + 32 < 40) out[row * 40 + lane + 32] = b2 - lse;
    }
}

// ---------------- launch ----------------
extern "C" void kernel_launch(void* const* d_in, const int* in_sizes, int n_in,
                              void* d_out, int out_size) {
    const float* real = (const float*)d_in[0];
    const float* imag = (const float*)d_in[1];
    const int*   edges = (const int*)d_in[2];
    const float* qp = (const float*)d_in[3];
    const float* ew = (const float*)d_in[4];
    const float* W1 = (const float*)d_in[5];
    const float* b1 = (const float*)d_in[6];
    const float* W2 = (const float*)d_in[7];
    const float* b2 = (const float*)d_in[8];
    const float* Wc = (const float*)d_in[9];
    const float* bc = (const float*)d_in[10];
    float* out = (float*)d_out;
    int E = in_sizes[4];

    float *Z1r, *Z1i, *Z2r, *Z2i, *H1r, *H1i, *H2r, *H2i;
    cudaGetSymbolAddress((void**)&Z1r, g_Z1r);
    cudaGetSymbolAddress((void**)&Z1i, g_Z1i);
    cudaGetSymbolAddress((void**)&Z2r, g_Z2r);
    cudaGetSymbolAddress((void**)&Z2i, g_Z2i);
    cudaGetSymbolAddress((void**)&H1r, g_H1r);
    cudaGetSymbolAddress((void**)&H1i, g_H1i);
    cudaGetSymbolAddress((void**)&H2r, g_H2r);
    cudaGetSymbolAddress((void**)&H2i, g_H2i);

    zero_kernel<<<NE / 4 / 256, 256>>>();
    scatter_kernel<<<(E + 255) / 256, 256>>>(edges, ew, E);
    colsum_kernel<<<dim3(NN / 256, 32), 256>>>();
    rowsum_kernel<<<NN, 256>>>();
    dinv_kernel<<<NN / 256, 256>>>();
    build_ell_kernel<<<dim3(NN / 32, NN / 32), dim3(32, 8)>>>(qp);

    // ---- layer 1 (Z0 = input) ----
    spmm_kernel<<<NN, 256>>>(real, imag, nullptr, nullptr, Z1r, Z1i);          // Z1 = Lc@X
    spmm_kernel<<<NN, 256>>>(Z1r, Z1i, real, imag, Z2r, Z2i);                  // Z2 = 2Lc@Z1 - Z0
    // Yc = i*S  =>  out_i = S_re + b ; out_r = -S_im + b
    gemm3_kernel<<<dim3(4, 32), 256>>>(real, Z1r, Z2r, W1, b1,  1.f, H1i);
    gemm3_kernel<<<dim3(4, 32), 256>>>(imag, Z1i, Z2i, W1, b1, -1.f, H1r);

    // ---- layer 2 (Z0 = H1) ----
    spmm_kernel<<<NN, 256>>>(H1r, H1i, nullptr, nullptr, Z1r, Z1i);
    spmm_kernel<<<NN, 256>>>(Z1r, Z1i, H1r, H1i, Z2r, Z2i);
    gemm3_kernel<<<dim3(4, 32), 256>>>(H1r, Z1r, Z2r, W2, b2,  1.f, H2i);
    gemm3_kernel<<<dim3(4, 32), 256>>>(H1i, Z1i, Z2i, W2, b2, -1.f, H2r);

    classifier_kernel<<<NN, 128>>>(H2r, H2i, Wc, bc, out);
}

// round 2
// speedup vs baseline: 1.9813x; 1.9813x over previous
#include <cuda_runtime.h>
#include <cuda_bf16.h>
#include <math.h>

#define NN   4096
#define FF   256
#define ELLW 256
#define TBITS 19
#define TSIZE (1 << TBITS)
#define TMASK (TSIZE - 1)

// ---------------- scratch (device globals) ----------------
__device__ int   g_hkey[TSIZE];
__device__ float g_hval[TSIZE];
__device__ float g_deg[NN];
__device__ float g_dinv[NN];
__device__ int   g_cnt[NN];
__device__ int   g_col[NN * ELLW];
__device__ float g_lre[NN * ELLW];
__device__ float g_lim[NN * ELLW];
__device__ float g_Z1r[NN * FF], g_Z1i[NN * FF];
__device__ float g_Z2r[NN * FF], g_Z2i[NN * FF];
__device__ float g_H1r[NN * FF], g_H1i[NN * FF];
__device__ float g_H2r[NN * FF], g_H2i[NN * FF];

__device__ __forceinline__ unsigned hash_key(int key) {
    return ((unsigned)key * 2654435761u) >> (32 - TBITS);
}

// ---------------- graph build (hash-based, no dense A) ----------------
__global__ void zero_kernel() {
    int idx = blockIdx.x * blockDim.x + threadIdx.x;
    if (idx < TSIZE) { g_hkey[idx] = -1; g_hval[idx] = 0.f; }
    if (idx < NN)    { g_deg[idx] = 0.f; g_cnt[idx] = 0; }
}

__global__ void insert_kernel(const int* __restrict__ edges,
                              const float* __restrict__ w, int E) {
    int e = blockIdx.x * blockDim.x + threadIdx.x;
    if (e >= E) return;
    int r = edges[e];
    int c = edges[E + e];
    float we = w[e];
    atomicAdd(&g_deg[r], 0.5f * we);
    atomicAdd(&g_deg[c], 0.5f * we);
    int key = (r << 12) | c;
    unsigned h = hash_key(key) & TMASK;
    while (true) {
        int prev = atomicCAS(&g_hkey[h], -1, key);
        if (prev == -1 || prev == key) { atomicAdd(&g_hval[h], we); break; }
        h = (h + 1) & TMASK;
    }
}

__global__ void dinv_kernel() {
    int i = blockIdx.x * blockDim.x + threadIdx.x;
    if (i < NN) {
        float d = g_deg[i];
        if (d == 0.f) d = 1.f;
        g_dinv[i] = rsqrtf(d);
    }
}

__device__ __forceinline__ float hash_lookup(int key, bool* found) {
    unsigned h = hash_key(key) & TMASK;
    while (true) {
        int k = g_hkey[h];
        if (k == key) { *found = true; return g_hval[h]; }
        if (k == -1)  { *found = false; return 0.f; }
        h = (h + 1) & TMASK;
    }
}

__device__ __forceinline__ void ell_push(int r, int c, float lre, float lim) {
    int slot = atomicAdd(&g_cnt[r], 1);
    if (slot < ELLW) {
        g_col[r * ELLW + slot] = c;
        g_lre[r * ELLW + slot] = lre;
        g_lim[r * ELLW + slot] = lim;
    }
}

__global__ void emit_kernel(const float* __restrict__ qp) {
    int s = blockIdx.x * blockDim.x + threadIdx.x;
    if (s >= TSIZE) return;
    int key = g_hkey[s];
    if (key < 0) return;
    int i = key >> 12;
    int j = key & 4095;
    float a = g_hval[s];
    float q = __ldg(qp);
    if (i == j) {
        float di = g_dinv[i];
        float an = di * di * a;
        ell_push(i, i, -an, 0.f);
        return;
    }
    bool found;
    float at = hash_lookup((j << 12) | i, &found);
    if (i > j && found) return;   // handled by the (j,i) slot
    float asym = 0.5f * (a + at);
    float an = g_dinv[i] * asym * g_dinv[j];
    float th = 6.283185307179586f * q * (a - at);
    float sn, cs;
    sincosf(th, &sn, &cs);
    // conj(L)[i][j] = -A_n * exp(-i*th)  -> ( -an*cs , +an*sn )
    ell_push(i, j, -an * cs,  an * sn);
    ell_push(j, i, -an * cs, -an * sn);
}

// ---------------- complex SpMM (ELL) ----------------
__global__ void spmm_kernel(const float* __restrict__ Xr, const float* __restrict__ Xi,
                            const float* __restrict__ Sr, const float* __restrict__ Si,
                            float* __restrict__ Yr, float* __restrict__ Yi) {
    int row = blockIdx.x;
    int t = threadIdx.x;
    int cnt = g_cnt[row];
    if (cnt > ELLW) cnt = ELLW;
    __shared__ int   sc[ELLW];
    __shared__ float slr[ELLW];
    __shared__ float sli[ELLW];
    for (int k = t; k < cnt; k += 256) {
        sc [k] = g_col[row * ELLW + k];
        slr[k] = g_lre[row * ELLW + k];
        sli[k] = g_lim[row * ELLW + k];
    }
    __syncthreads();
    float ar = 0.f, ai = 0.f;
    #pragma unroll 4
    for (int k = 0; k < cnt; k++) {
        int   c  = sc[k];
        float lr = slr[k];
        float li = sli[k];
        float xr = __ldg(&Xr[c * FF + t]);
        float xi = __ldg(&Xi[c * FF + t]);
        ar = fmaf(lr, xr, ar);
        ar = fmaf(-li, xi, ar);
        ai = fmaf(lr, xi, ai);
        ai = fmaf(li, xr, ai);
    }
    int o = row * FF + t;
    if (Sr) {
        Yr[o] = 2.f * ar - Sr[o];
        Yi[o] = 2.f * ai - Si[o];
    } else {
        Yr[o] = ar;
        Yi[o] = ai;
    }
}

// ---------------- fused tensor-core GEMM (bf16 3-term split) ----------------
// C[8192,256] = [Zr;Zi](8192x768) @ Wcat(768x256); rows<4096 -> Hi=C+b, rows>=4096 -> Hr=-C+b
// BM=128, BN=64, BK=32; 256 thr = 8 warps (2m x 4n); warp tile 64x16.

__device__ __forceinline__ unsigned pack_bf2(float x, float y) {
    __nv_bfloat162 t;
    t.x = __float2bfloat16_rn(x);
    t.y = __float2bfloat16_rn(y);
    return *reinterpret_cast<unsigned*>(&t);
}

#define MMA_BF16(d, a, b)                                                        \
    asm volatile("mma.sync.aligned.m16n8k16.row.col.f32.bf16.bf16.f32 "          \
                 "{%0,%1,%2,%3},{%4,%5,%6,%7},{%8,%9},{%0,%1,%2,%3};"            \
                 : "+f"(d[0]), "+f"(d[1]), "+f"(d[2]), "+f"(d[3])                 \
                 : "r"(a[0]), "r"(a[1]), "r"(a[2]), "r"(a[3]), "r"(b[0]), "r"(b[1]))

#define LDSM_X4(r, addr)                                                         \
    asm volatile("ldmatrix.sync.aligned.m8n8.x4.shared.b16 {%0,%1,%2,%3}, [%4];" \
                 : "=r"(r[0]), "=r"(r[1]), "=r"(r[2]), "=r"(r[3]) : "r"(addr) : "memory")

#define LDSM_X4_T(r, addr)                                                             \
    asm volatile("ldmatrix.sync.aligned.m8n8.x4.trans.shared.b16 {%0,%1,%2,%3}, [%4];" \
                 : "=r"(r[0]), "=r"(r[1]), "=r"(r[2]), "=r"(r[3]) : "r"(addr) : "memory")

#define AST 20   // A smem row stride in uints (40 bf16 = 80B, LDSM conflict-free)
#define WST 36   // W smem row stride in uints (72 bf16 = 144B, LDSM.T conflict-free)

__global__ void __launch_bounds__(256, 2)
gemm_fused_kernel(const float* __restrict__ A0r, const float* __restrict__ A1r,
                  const float* __restrict__ A2r, const float* __restrict__ A0i,
                  const float* __restrict__ A1i, const float* __restrict__ A2i,
                  const float* __restrict__ W, const float* __restrict__ bias,
                  float* __restrict__ Hr, float* __restrict__ Hi) {
    __shared__ unsigned ash[128 * AST], asl[128 * AST];
    __shared__ unsigned wsh[32 * WST],  wsl[32 * WST];

    int tid = threadIdx.x;
    int lane = tid & 31;
    int warp = tid >> 5;
    int wm = warp >> 2;          // 0..1
    int wn = warp & 3;           // 0..3
    int m0 = blockIdx.y * 128;   // 0..8064
    int n0 = blockIdx.x * 64;
    bool isImag = (m0 >= 4096);
    int mrow0 = m0 & 4095;

    float acc[4][2][4];
    #pragma unroll
    for (int mt = 0; mt < 4; mt++)
        #pragma unroll
        for (int nt = 0; nt < 2; nt++)
            #pragma unroll
            for (int r = 0; r < 4; r++) acc[mt][nt][r] = 0.f;

    unsigned a_hi_base = (unsigned)__cvta_generic_to_shared(ash);
    unsigned a_lo_base = (unsigned)__cvta_generic_to_shared(asl);
    unsigned w_hi_base = (unsigned)__cvta_generic_to_shared(wsh);
    unsigned w_lo_base = (unsigned)__cvta_generic_to_shared(wsl);

    // per-lane LDSM byte offsets (h added later)
    unsigned a_off = ((wm * 64 + (lane & 15)) * (AST * 2) + (lane >> 4) * 8) * 2;
    unsigned w_off = (((((lane >> 3) & 1) * 8 + (lane & 7)) * (WST * 2)) + wn * 16 + (lane >> 4) * 8) * 2;

    for (int ks = 0; ks < 24; ks++) {
        int k0 = ks * 32;
        int plane = k0 >> 8;
        int kc = k0 & 255;
        const float* Ap = isImag ? (plane == 0 ? A0i : (plane == 1 ? A1i : A2i))
                                 : (plane == 0 ? A0r : (plane == 1 ? A1r : A2r));
        // load A tile 128x32
        #pragma unroll
        for (int t = 0; t < 4; t++) {
            int idx = tid + t * 256;
            int r = idx >> 3;
            int c4 = (idx & 7) * 4;
            float4 v = *reinterpret_cast<const float4*>(&Ap[(mrow0 + r) * 256 + kc + c4]);
            float hx = __bfloat162float(__float2bfloat16_rn(v.x));
            float hy = __bfloat162float(__float2bfloat16_rn(v.y));
            float hz = __bfloat162float(__float2bfloat16_rn(v.z));
            float hw = __bfloat162float(__float2bfloat16_rn(v.w));
            int o = r * AST + (c4 >> 1);
            ash[o]     = pack_bf2(v.x, v.y);
            ash[o + 1] = pack_bf2(v.z, v.w);
            asl[o]     = pack_bf2(v.x - hx, v.y - hy);
            asl[o + 1] = pack_bf2(v.z - hz, v.w - hw);
        }
        // load W tile 32x64 (k-major)
        #pragma unroll
        for (int t = 0; t < 2; t++) {
            int idx = tid + t * 256;
            int kk = idx >> 4;
            int n4 = (idx & 15) * 4;
            float4 v = *reinterpret_cast<const float4*>(&W[plane * 65536 + (kc + kk) * 256 + n0 + n4]);
            float hx = __bfloat162float(__float2bfloat16_rn(v.x));
            float hy = __bfloat162float(__float2bfloat16_rn(v.y));
            float hz = __bfloat162float(__float2bfloat16_rn(v.z));
            float hw = __bfloat162float(__float2bfloat16_rn(v.w));
            int o = kk * WST + (n4 >> 1);
            wsh[o]     = pack_bf2(v.x, v.y);
            wsh[o + 1] = pack_bf2(v.z, v.w);
            wsl[o]     = pack_bf2(v.x - hx, v.y - hy);
            wsl[o + 1] = pack_bf2(v.z - hz, v.w - hw);
        }
        __syncthreads();

        #pragma unroll
        for (int h = 0; h < 32; h += 16) {
            unsigned ah[4][4], al[4][4];
            #pragma unroll
            for (int mt = 0; mt < 4; mt++) {
                unsigned off = a_off + (mt * 16 * AST * 2 + h) * 2;
                LDSM_X4(ah[mt], a_hi_base + off);
                LDSM_X4(al[mt], a_lo_base + off);
            }
            unsigned bh4[4], bl4[4];
            {
                unsigned off = w_off + (h * WST * 2) * 2;
                LDSM_X4_T(bh4, w_hi_base + off);
                LDSM_X4_T(bl4, w_lo_base + off);
            }
            #pragma unroll
            for (int mt = 0; mt < 4; mt++) {
                #pragma unroll
                for (int nt = 0; nt < 2; nt++) {
                    unsigned bh[2] = {bh4[nt * 2], bh4[nt * 2 + 1]};
                    unsigned bl[2] = {bl4[nt * 2], bl4[nt * 2 + 1]};
                    MMA_BF16(acc[mt][nt], ah[mt], bh);
                    MMA_BF16(acc[mt][nt], ah[mt], bl);
                    MMA_BF16(acc[mt][nt], al[mt], bh);
                }
            }
        }
        __syncthreads();
    }

    // epilogue
    int g = lane >> 2, tig = lane & 3;
    #pragma unroll
    for (int mt = 0; mt < 4; mt++) {
        #pragma unroll
        for (int nt = 0; nt < 2; nt++) {
            int n = n0 + wn * 16 + nt * 8 + tig * 2;
            float b0 = bias[n], b1v = bias[n + 1];
            int ml0 = mrow0 + wm * 64 + mt * 16 + g;
            float* c0 = acc[mt][nt];
            if (!isImag) {
                float2 o0 = make_float2(c0[0] + b0, c0[1] + b1v);
                float2 o1 = make_float2(c0[2] + b0, c0[3] + b1v);
                *reinterpret_cast<float2*>(&Hi[ml0 * 256 + n])       = o0;
                *reinterpret_cast<float2*>(&Hi[(ml0 + 8) * 256 + n]) = o1;
            } else {
                float2 o0 = make_float2(-c0[0] + b0, -c0[1] + b1v);
                float2 o1 = make_float2(-c0[2] + b0, -c0[3] + b1v);
                *reinterpret_cast<float2*>(&Hr[ml0 * 256 + n])       = o0;
                *reinterpret_cast<float2*>(&Hr[(ml0 + 8) * 256 + n]) = o1;
            }
        }
    }
}

// ---------------- classifier + log_softmax ----------------
__global__ void classifier_kernel(const float* __restrict__ Hr, const float* __restrict__ Hi,
                                  const float* __restrict__ Wc, const float* __restrict__ bc,
                                  float* __restrict__ out) {
    int row = blockIdx.x;
    int t = threadIdx.x;   // 128
    __shared__ float x[512];
    __shared__ float lg[40];
    for (int i = t; i < 256; i += 128) {
        x[i]       = Hr[row * 256 + i];
        x[i + 256] = Hi[row * 256 + i];
    }
    __syncthreads();
    int warp = t >> 5, lane = t & 31;
    for (int c = warp; c < 40; c += 4) {
        float s = 0.f;
        #pragma unroll
        for (int k = lane; k < 512; k += 32) s = fmaf(x[k], Wc[c * 512 + k], s);
        #pragma unroll
        for (int o = 16; o > 0; o >>= 1) s += __shfl_xor_sync(0xffffffffu, s, o);
        if (lane == 0) lg[c] = s + bc[c];
    }
    __syncthreads();
    if (warp == 0) {
        float a  = (lane < 40)      ? lg[lane]      : -3.4e38f;
        float b2 = (lane + 32 < 40) ? lg[lane + 32] : -3.4e38f;
        float m = fmaxf(a, b2);
        #pragma unroll
        for (int o = 16; o > 0; o >>= 1) m = fmaxf(m, __shfl_xor_sync(0xffffffffu, m, o));
        float s = ((lane < 40) ? expf(a - m) : 0.f) + ((lane + 32 < 40) ? expf(b2 - m) : 0.f);
        #pragma unroll
        for (int o = 16; o > 0; o >>= 1) s += __shfl_xor_sync(0xffffffffu, s, o);
        float lse = m + logf(s);
        if (lane < 40)      out[row * 40 + lane]      = a - lse;
        if (lane + 32 < 40) out[row * 40 + lane + 32] = b2 - lse;
    }
}

// ---------------- launch ----------------
extern "C" void kernel_launch(void* const* d_in, const int* in_sizes, int n_in,
                              void* d_out, int out_size) {
    const float* real = (const float*)d_in[0];
    const float* imag = (const float*)d_in[1];
    const int*   edges = (const int*)d_in[2];
    const float* qp = (const float*)d_in[3];
    const float* ew = (const float*)d_in[4];
    const float* W1 = (const float*)d_in[5];
    const float* b1 = (const float*)d_in[6];
    const float* W2 = (const float*)d_in[7];
    const float* b2 = (const float*)d_in[8];
    const float* Wc = (const float*)d_in[9];
    const float* bc = (const float*)d_in[10];
    float* out = (float*)d_out;
    int E = in_sizes[4];

    float *Z1r, *Z1i, *Z2r, *Z2i, *H1r, *H1i, *H2r, *H2i;
    cudaGetSymbolAddress((void**)&Z1r, g_Z1r);
    cudaGetSymbolAddress((void**)&Z1i, g_Z1i);
    cudaGetSymbolAddress((void**)&Z2r, g_Z2r);
    cudaGetSymbolAddress((void**)&Z2i, g_Z2i);
    cudaGetSymbolAddress((void**)&H1r, g_H1r);
    cudaGetSymbolAddress((void**)&H1i, g_H1i);
    cudaGetSymbolAddress((void**)&H2r, g_H2r);
    cudaGetSymbolAddress((void**)&H2i, g_H2i);

    zero_kernel<<<TSIZE / 256, 256>>>();
    insert_kernel<<<(E + 255) / 256, 256>>>(edges, ew, E);
    dinv_kernel<<<NN / 256, 256>>>();
    emit_kernel<<<TSIZE / 256, 256>>>(qp);

    // ---- layer 1 ----
    spmm_kernel<<<NN, 256>>>(real, imag, nullptr, nullptr, Z1r, Z1i);
    spmm_kernel<<<NN, 256>>>(Z1r, Z1i, real, imag, Z2r, Z2i);
    gemm_fused_kernel<<<dim3(4, 64), 256>>>(real, Z1r, Z2r, imag, Z1i, Z2i, W1, b1, H1r, H1i);

    // ---- layer 2 ----
    spmm_kernel<<<NN, 256>>>(H1r, H1i, nullptr, nullptr, Z1r, Z1i);
    spmm_kernel<<<NN, 256>>>(Z1r, Z1i, H1r, H1i, Z2r, Z2i);
    gemm_fused_kernel<<<dim3(4, 64), 256>>>(H1r, Z1r, Z2r, H1i, Z1i, Z2i, W2, b2, H2r, H2i);

    classifier_kernel<<<NN, 128>>>(H2r, H2i, Wc, bc, out);
}